// round 1
// baseline (speedup 1.0000x reference)
#include <cuda_runtime.h>
#include <math.h>

#define D       768
#define NR      14
#define NB      8192
#define M_TOTAL (NB * NR)          // 114688

// Scratch for projected features P = X@W + b  : [M_TOTAL, D] fp32 = 352 MB
__device__ float g_P[(size_t)M_TOTAL * D];

// ---------------------------------------------------------------------------
// Kernel 1: C[m,e] = sum_d A[m,d] * W[d,e] + b[e]
// 128x128 block tile, K-tile 8, 256 threads, 8x8 per-thread microtile.
// M=114688 (896 tiles), N=768 (6 tiles), K=768 — all exact, no bounds checks.
// ---------------------------------------------------------------------------
__global__ __launch_bounds__(256) void gemm_bias_kernel(
    const float* __restrict__ A, const float* __restrict__ W,
    const float* __restrict__ bias)
{
    __shared__ float As[8][128];   // [k][m]
    __shared__ float Bs[8][128];   // [k][n]

    const int t  = threadIdx.x;
    const int bm = blockIdx.y * 128;
    const int bn = blockIdx.x * 128;

    // global-load mapping
    const int ar = t >> 1;            // 0..127  (A row in tile)
    const int ac = (t & 1) << 2;      // 0 or 4  (A col in k-tile)
    const int br = t >> 5;            // 0..7    (W row in k-tile)
    const int bc = (t & 31) << 2;     // 0..124  (W col in tile)

    const float* Aptr = A + (size_t)(bm + ar) * D + ac;
    const float* Wptr = W + (size_t)br * D + bn + bc;

    // compute mapping
    const int ty = (t >> 4) << 3;     // 0..120 step 8
    const int tx = (t & 15) << 3;     // 0..120 step 8

    float acc[8][8];
#pragma unroll
    for (int i = 0; i < 8; i++)
#pragma unroll
        for (int j = 0; j < 8; j++) acc[i][j] = 0.f;

    for (int k0 = 0; k0 < D; k0 += 8) {
        float4 av = *(const float4*)(Aptr + k0);
        float4 wv = *(const float4*)(Wptr + (size_t)k0 * D);
        As[ac + 0][ar] = av.x;
        As[ac + 1][ar] = av.y;
        As[ac + 2][ar] = av.z;
        As[ac + 3][ar] = av.w;
        *(float4*)&Bs[br][bc] = wv;
        __syncthreads();

#pragma unroll
        for (int k = 0; k < 8; k++) {
            float4 a0 = *(const float4*)&As[k][ty];
            float4 a1 = *(const float4*)&As[k][ty + 4];
            float4 b0 = *(const float4*)&Bs[k][tx];
            float4 b1 = *(const float4*)&Bs[k][tx + 4];
            float a[8]  = {a0.x, a0.y, a0.z, a0.w, a1.x, a1.y, a1.z, a1.w};
            float bb[8] = {b0.x, b0.y, b0.z, b0.w, b1.x, b1.y, b1.z, b1.w};
#pragma unroll
            for (int i = 0; i < 8; i++)
#pragma unroll
                for (int j = 0; j < 8; j++)
                    acc[i][j] = fmaf(a[i], bb[j], acc[i][j]);
        }
        __syncthreads();
    }

    float bz[8];
#pragma unroll
    for (int j = 0; j < 8; j++) bz[j] = bias[bn + tx + j];

#pragma unroll
    for (int i = 0; i < 8; i++) {
        float4 v0, v1;
        v0.x = acc[i][0] + bz[0];
        v0.y = acc[i][1] + bz[1];
        v0.z = acc[i][2] + bz[2];
        v0.w = acc[i][3] + bz[3];
        v1.x = acc[i][4] + bz[4];
        v1.y = acc[i][5] + bz[5];
        v1.z = acc[i][6] + bz[6];
        v1.w = acc[i][7] + bz[7];
        float* crow = g_P + (size_t)(bm + ty + i) * D + bn + tx;
        *(float4*)(crow)     = v0;
        *(float4*)(crow + 4) = v1;
    }
}

// ---------------------------------------------------------------------------
// Kernel 2: per-batch epilogue.
//   S = P_b P_b^T (Gram, 14x14 over K=768)
//   sim = S / (norm_i * norm_j),  norm_i = max(sqrt(S_ii), 1e-12)
//   aw  = a_i a_j / ((max_i a_i)^2 + 1e-8)
//   cw  = co / (sum(co) + 1e-8)
//   out = softmax_rows(sim * aw * cw)
// One 256-thread CTA per batch. P tile staged in smem with row stride 772.
// ---------------------------------------------------------------------------
__global__ __launch_bounds__(256) void epilogue_kernel(
    const float* __restrict__ area, const float* __restrict__ co,
    float* __restrict__ out)
{
    __shared__ float Pb[NR * 772];   // 14 rows, stride 772 (bank-conflict pad)
    __shared__ float S[256];         // 16x16 padded Gram
    __shared__ float adj[196];       // co tile -> adj -> exp values
    __shared__ float a_s[NR];
    __shared__ float norm_s[NR];
    __shared__ float rinv[NR];
    __shared__ float amax_s;
    __shared__ float csum_s;

    const int b = blockIdx.x;
    const int t = threadIdx.x;

    S[t] = 0.f;
    if (t == 0) csum_s = 0.f;

    // stage P_b (14 x 768) into smem, float4, coalesced
    const float4* src = (const float4*)(g_P + (size_t)b * (NR * D));
    for (int idx = t; idx < NR * (D / 4); idx += 256) {
        int r  = idx / (D / 4);
        int c4 = idx - r * (D / 4);
        *(float4*)&Pb[r * 772 + (c4 << 2)] = src[idx];
    }

    float co_v = 0.f;
    if (t < 196) { co_v = co[t]; adj[t] = co_v; }
    if (t < NR)  a_s[t] = area[b * NR + t];
    __syncthreads();

    // sum(co) and max(area) (areas are uniform[0,1) >= 0, so 0 is a safe fill)
    if (t < 196) atomicAdd(&csum_s, co_v);
    if (t < 32) {
        float v = (t < NR) ? a_s[t] : 0.f;
#pragma unroll
        for (int o = 16; o > 0; o >>= 1)
            v = fmaxf(v, __shfl_xor_sync(0xffffffffu, v, o));
        if (t == 0) amax_s = v;
    }

    // ---- Gram: 2x2 pair tiles (8x8 tile grid over 16x16 padded), 4-way K split
    const int q  = t >> 6;            // k-quarter 0..3
    const int p  = t & 63;            // tile id
    const int i0 = (p >> 3) << 1;     // 0..14 step 2
    const int j0 = (p & 7) << 1;      // 0..14 step 2

    const float4* A0 = (const float4*)(Pb + min(i0, 13) * 772);
    const float4* A1 = (const float4*)(Pb + min(i0 + 1, 13) * 772);
    const float4* B0 = (const float4*)(Pb + min(j0, 13) * 772);
    const float4* B1 = (const float4*)(Pb + min(j0 + 1, 13) * 772);

    float s00 = 0.f, s01 = 0.f, s10 = 0.f, s11 = 0.f;
    const int kb = q * 48;            // 48 float4 = 192 floats per quarter
#pragma unroll 4
    for (int k = kb; k < kb + 48; k++) {
        float4 a0 = A0[k], a1 = A1[k], b0 = B0[k], b1 = B1[k];
        s00 += a0.x * b0.x + a0.y * b0.y + a0.z * b0.z + a0.w * b0.w;
        s01 += a0.x * b1.x + a0.y * b1.y + a0.z * b1.z + a0.w * b1.w;
        s10 += a1.x * b0.x + a1.y * b0.y + a1.z * b0.z + a1.w * b0.w;
        s11 += a1.x * b1.x + a1.y * b1.y + a1.z * b1.z + a1.w * b1.w;
    }
    if (i0 < NR) {
        if (j0 < NR)     atomicAdd(&S[i0 * 16 + j0],     s00);
        if (j0 + 1 < NR) atomicAdd(&S[i0 * 16 + j0 + 1], s01);
    }
    if (i0 + 1 < NR) {
        if (j0 < NR)     atomicAdd(&S[(i0 + 1) * 16 + j0],     s10);
        if (j0 + 1 < NR) atomicAdd(&S[(i0 + 1) * 16 + j0 + 1], s11);
    }
    __syncthreads();

    if (t < NR) norm_s[t] = fmaxf(sqrtf(S[t * 16 + t]), 1e-12f);
    __syncthreads();

    if (t < 196) {
        int i = t / NR, j = t - i * NR;
        float sim = S[i * 16 + j] / (norm_s[i] * norm_s[j]);
        float awf = a_s[i] * a_s[j] / (amax_s * amax_s + 1e-8f);
        float cwf = adj[t] / (csum_s + 1e-8f);
        adj[t] = sim * awf * cwf;
    }
    __syncthreads();

    if (t < NR) {
        float m = -1e30f;
#pragma unroll
        for (int j = 0; j < NR; j++) m = fmaxf(m, adj[t * NR + j]);
        float s = 0.f;
#pragma unroll
        for (int j = 0; j < NR; j++) {
            float e = expf(adj[t * NR + j] - m);
            adj[t * NR + j] = e;
            s += e;
        }
        rinv[t] = 1.f / s;
    }
    __syncthreads();

    if (t < 196) out[(size_t)b * 196 + t] = adj[t] * rinv[t / NR];
}

extern "C" void kernel_launch(void* const* d_in, const int* in_sizes, int n_in,
                              void* d_out, int out_size)
{
    const float* X    = (const float*)d_in[0];  // [8192,14,768]
    const float* area = (const float*)d_in[1];  // [8192,14]
    const float* co   = (const float*)d_in[2];  // [14,14]
    const float* W    = (const float*)d_in[3];  // [768,768]
    const float* bias = (const float*)d_in[4];  // [768]
    float* out = (float*)d_out;                 // [8192,14,14]

    dim3 g1(D / 128, M_TOTAL / 128);            // (6, 896)
    gemm_bias_kernel<<<g1, 256>>>(X, W, bias);
    epilogue_kernel<<<NB, 256>>>(area, co, out);
}

// round 4
// speedup vs baseline: 4.2761x; 4.2761x over previous
#include <cuda_runtime.h>
#include <cuda_bf16.h>
#include <math.h>
#include <stdint.h>

#define D       768
#define NR      14
#define NB      8192
#define M_TOTAL (NB * NR)          // 114688

// ---------------------------------------------------------------------------
// Device-global scratch (no allocations allowed)
// ---------------------------------------------------------------------------
__device__ float         g_P [(size_t)M_TOTAL * D];   // projected feats fp32 (352 MB)
__device__ __nv_bfloat16 g_Xb[(size_t)M_TOTAL * D];   // X in bf16 (176 MB)
__device__ __nv_bfloat16 g_Wt[(size_t)D * D];         // W^T in bf16 [n][k]

// ---------------------------------------------------------------------------
// Helpers
// ---------------------------------------------------------------------------
__device__ __forceinline__ uint32_t smem_u32(const void* p) {
    uint32_t a;
    asm("{ .reg .u64 t; cvta.to.shared.u64 t, %1; cvt.u32.u64 %0, t; }" : "=r"(a) : "l"(p));
    return a;
}
#define SW128(o) ((o) ^ ((((uint32_t)(o)) >> 3) & 0x70u))

__device__ __forceinline__ void cpa16(uint32_t dst, const void* src) {
    asm volatile("cp.async.cg.shared.global [%0], [%1], 16;" :: "r"(dst), "l"(src));
}
#define CP_COMMIT() asm volatile("cp.async.commit_group;" ::: "memory")
#define CP_WAIT2()  asm volatile("cp.async.wait_group 2;"  ::: "memory")

__device__ __forceinline__ void ldm_x4(uint32_t* r, uint32_t addr) {
    asm volatile("ldmatrix.sync.aligned.m8n8.x4.shared.b16 {%0,%1,%2,%3}, [%4];"
                 : "=r"(r[0]), "=r"(r[1]), "=r"(r[2]), "=r"(r[3]) : "r"(addr));
}
__device__ __forceinline__ void mma16816(float* d, const uint32_t* a,
                                         uint32_t b0, uint32_t b1) {
    asm volatile(
        "mma.sync.aligned.m16n8k16.row.col.f32.bf16.bf16.f32 "
        "{%0,%1,%2,%3}, {%4,%5,%6,%7}, {%8,%9}, {%0,%1,%2,%3};"
        : "+f"(d[0]), "+f"(d[1]), "+f"(d[2]), "+f"(d[3])
        : "r"(a[0]), "r"(a[1]), "r"(a[2]), "r"(a[3]), "r"(b0), "r"(b1));
}

// ---------------------------------------------------------------------------
// Conversion kernels
// ---------------------------------------------------------------------------
__global__ __launch_bounds__(256) void convertX(const float* __restrict__ X) {
    size_t base = ((size_t)blockIdx.x * 256 + threadIdx.x) * 8;
    float4 f0 = *(const float4*)(X + base);
    float4 f1 = *(const float4*)(X + base + 4);
    __nv_bfloat162 b0 = __float22bfloat162_rn(make_float2(f0.x, f0.y));
    __nv_bfloat162 b1 = __float22bfloat162_rn(make_float2(f0.z, f0.w));
    __nv_bfloat162 b2 = __float22bfloat162_rn(make_float2(f1.x, f1.y));
    __nv_bfloat162 b3 = __float22bfloat162_rn(make_float2(f1.z, f1.w));
    uint4 v;
    v.x = *(uint32_t*)&b0; v.y = *(uint32_t*)&b1;
    v.z = *(uint32_t*)&b2; v.w = *(uint32_t*)&b3;
    *(uint4*)(g_Xb + base) = v;
}

__global__ void transposeW(const float* __restrict__ W) {
    __shared__ float tile[32][33];
    int x = blockIdx.x * 32 + threadIdx.x;
    int y = blockIdx.y * 32 + threadIdx.y;
#pragma unroll
    for (int j = 0; j < 32; j += 8)
        tile[threadIdx.y + j][threadIdx.x] = W[(size_t)(y + j) * D + x];
    __syncthreads();
    int xo = blockIdx.y * 32 + threadIdx.x;
    int yo = blockIdx.x * 32 + threadIdx.y;
#pragma unroll
    for (int j = 0; j < 32; j += 8)
        g_Wt[(size_t)(yo + j) * D + xo] = __float2bfloat16(tile[threadIdx.x][threadIdx.y + j]);
}

// ---------------------------------------------------------------------------
// HMMA (mma.sync) GEMM:  P[m,n] = sum_k Xb[m,k] * Wt[n,k] + bias[n]
// BM=128, BN=128, BK=64, 3-stage cp.async, 256 threads (8 warps, 4x2 grid,
// warp tile 32x64). SW128 swizzle, ldmatrix.x4 fragment loads.
// ---------------------------------------------------------------------------
#define BK          64
#define NKIT        (D / BK)           // 12
#define STAGE_BYTES 32768              // A 16KB + B 16KB
#define NSTAGES     3
#define GSMEM       (NSTAGES * STAGE_BYTES)   // 96KB

__device__ __forceinline__ void load_stage(uint32_t dst,
                                           const __nv_bfloat16* gA,
                                           const __nv_bfloat16* gB,
                                           int k0, int t) {
    // Full coverage: 128 rows x 8 chunks of 16B = 1024 chunks per operand.
#pragma unroll
    for (int i = 0; i < 4; i++) {
        int idx = t + i * 256;          // 0..1023
        int row = idx >> 3;             // 0..127
        int c16 = idx & 7;              // 16B chunk in 128B row
        uint32_t off = SW128((uint32_t)(row * 128 + c16 * 16));
        const __nv_bfloat16* sa = gA + (size_t)row * D + k0 + c16 * 8;
        const __nv_bfloat16* sb = gB + (size_t)row * D + k0 + c16 * 8;
        cpa16(dst + off, sa);
        cpa16(dst + 16384 + off, sb);
    }
}

__global__ __launch_bounds__(256, 2) void gemm_hmma(const float* __restrict__ bias) {
    extern __shared__ __align__(1024) char smem[];
    uint32_t sbase = smem_u32(smem);

    const int t  = threadIdx.x;
    const int w  = t >> 5;
    const int l  = t & 31;
    const int bn = blockIdx.x * 128;
    const int bm = blockIdx.y * 128;

    const int wm = (w >> 1) * 32;      // 0,32,64,96
    const int wn = (w & 1) * 64;       // 0,64

    // lane-level ldmatrix addressing components
    const int rA = wm + (l & 15);
    const int cA = (l >> 4) * 8;
    const int rB = wn + (l & 7) + ((l >= 16) ? 8 : 0);
    const int cB = (l & 8) ? 8 : 0;

    const __nv_bfloat16* gA = g_Xb + (size_t)bm * D;
    const __nv_bfloat16* gB = g_Wt + (size_t)bn * D;

    float acc[2][8][4];
#pragma unroll
    for (int mt = 0; mt < 2; mt++)
#pragma unroll
        for (int nt = 0; nt < 8; nt++)
#pragma unroll
            for (int e = 0; e < 4; e++) acc[mt][nt][e] = 0.f;

    load_stage(sbase,               gA, gB, 0,  t); CP_COMMIT();
    load_stage(sbase + STAGE_BYTES, gA, gB, BK, t); CP_COMMIT();

    for (int k = 0; k < NKIT; k++) {
        if (k + 2 < NKIT)
            load_stage(sbase + ((k + 2) % NSTAGES) * STAGE_BYTES, gA, gB, (k + 2) * BK, t);
        CP_COMMIT();
        CP_WAIT2();
        __syncthreads();

        uint32_t stA = sbase + (k % NSTAGES) * STAGE_BYTES;
        uint32_t stB = stA + 16384;

#pragma unroll
        for (int ks = 0; ks < 4; ks++) {
            uint32_t af[2][4];
#pragma unroll
            for (int mt = 0; mt < 2; mt++) {
                uint32_t off = SW128((uint32_t)((rA + mt * 16) * 128 + (ks * 16 + cA) * 2));
                ldm_x4(af[mt], stA + off);
            }
            uint32_t bf[4][4];
#pragma unroll
            for (int g = 0; g < 4; g++) {
                uint32_t off = SW128((uint32_t)((rB + g * 16) * 128 + (ks * 16 + cB) * 2));
                ldm_x4(bf[g], stB + off);
            }
#pragma unroll
            for (int mt = 0; mt < 2; mt++)
#pragma unroll
                for (int g = 0; g < 4; g++) {
                    mma16816(acc[mt][2 * g],     af[mt], bf[g][0], bf[g][1]);
                    mma16816(acc[mt][2 * g + 1], af[mt], bf[g][2], bf[g][3]);
                }
        }
        __syncthreads();
    }

    // epilogue: bias + store fp32
#pragma unroll
    for (int nt = 0; nt < 8; nt++) {
        int gn = bn + wn + nt * 8 + ((l & 3) * 2);
        float b0 = __ldg(bias + gn);
        float b1 = __ldg(bias + gn + 1);
#pragma unroll
        for (int mt = 0; mt < 2; mt++) {
            int gm = bm + wm + mt * 16 + (l >> 2);
            float2 v0 = make_float2(acc[mt][nt][0] + b0, acc[mt][nt][1] + b1);
            float2 v1 = make_float2(acc[mt][nt][2] + b0, acc[mt][nt][3] + b1);
            *(float2*)(g_P + (size_t)gm * D + gn)       = v0;
            *(float2*)(g_P + (size_t)(gm + 8) * D + gn) = v1;
        }
    }
}

// ---------------------------------------------------------------------------
// Per-batch epilogue (unchanged — 368us, verified)
// ---------------------------------------------------------------------------
__global__ __launch_bounds__(256) void epilogue_kernel(
    const float* __restrict__ area, const float* __restrict__ co,
    float* __restrict__ out)
{
    __shared__ float Pb[NR * 772];
    __shared__ float S[256];
    __shared__ float adj[196];
    __shared__ float a_s[NR];
    __shared__ float norm_s[NR];
    __shared__ float rinv[NR];
    __shared__ float amax_s;
    __shared__ float csum_s;

    const int b = blockIdx.x;
    const int t = threadIdx.x;

    S[t] = 0.f;
    if (t == 0) csum_s = 0.f;

    const float4* src = (const float4*)(g_P + (size_t)b * (NR * D));
    for (int idx = t; idx < NR * (D / 4); idx += 256) {
        int r  = idx / (D / 4);
        int c4 = idx - r * (D / 4);
        *(float4*)&Pb[r * 772 + (c4 << 2)] = src[idx];
    }

    float co_v = 0.f;
    if (t < 196) { co_v = co[t]; adj[t] = co_v; }
    if (t < NR)  a_s[t] = area[b * NR + t];
    __syncthreads();

    if (t < 196) atomicAdd(&csum_s, co_v);
    if (t < 32) {
        float v = (t < NR) ? a_s[t] : 0.f;
#pragma unroll
        for (int o = 16; o > 0; o >>= 1)
            v = fmaxf(v, __shfl_xor_sync(0xffffffffu, v, o));
        if (t == 0) amax_s = v;
    }

    const int q  = t >> 6;
    const int p  = t & 63;
    const int i0 = (p >> 3) << 1;
    const int j0 = (p & 7) << 1;

    const float4* A0 = (const float4*)(Pb + min(i0, 13) * 772);
    const float4* A1 = (const float4*)(Pb + min(i0 + 1, 13) * 772);
    const float4* B0 = (const float4*)(Pb + min(j0, 13) * 772);
    const float4* B1 = (const float4*)(Pb + min(j0 + 1, 13) * 772);

    float s00 = 0.f, s01 = 0.f, s10 = 0.f, s11 = 0.f;
    const int kb = q * 48;
#pragma unroll 4
    for (int k = kb; k < kb + 48; k++) {
        float4 a0 = A0[k], a1 = A1[k], b0 = B0[k], b1 = B1[k];
        s00 += a0.x * b0.x + a0.y * b0.y + a0.z * b0.z + a0.w * b0.w;
        s01 += a0.x * b1.x + a0.y * b1.y + a0.z * b1.z + a0.w * b1.w;
        s10 += a1.x * b0.x + a1.y * b0.y + a1.z * b0.z + a1.w * b0.w;
        s11 += a1.x * b1.x + a1.y * b1.y + a1.z * b1.z + a1.w * b1.w;
    }
    if (i0 < NR) {
        if (j0 < NR)     atomicAdd(&S[i0 * 16 + j0],     s00);
        if (j0 + 1 < NR) atomicAdd(&S[i0 * 16 + j0 + 1], s01);
    }
    if (i0 + 1 < NR) {
        if (j0 < NR)     atomicAdd(&S[(i0 + 1) * 16 + j0],     s10);
        if (j0 + 1 < NR) atomicAdd(&S[(i0 + 1) * 16 + j0 + 1], s11);
    }
    __syncthreads();

    if (t < NR) norm_s[t] = fmaxf(sqrtf(S[t * 16 + t]), 1e-12f);
    __syncthreads();

    if (t < 196) {
        int i = t / NR, j = t - i * NR;
        float sim = S[i * 16 + j] / (norm_s[i] * norm_s[j]);
        float awf = a_s[i] * a_s[j] / (amax_s * amax_s + 1e-8f);
        float cwf = adj[t] / (csum_s + 1e-8f);
        adj[t] = sim * awf * cwf;
    }
    __syncthreads();

    if (t < NR) {
        float m = -1e30f;
#pragma unroll
        for (int j = 0; j < NR; j++) m = fmaxf(m, adj[t * NR + j]);
        float s = 0.f;
#pragma unroll
        for (int j = 0; j < NR; j++) {
            float e = expf(adj[t * NR + j] - m);
            adj[t * NR + j] = e;
            s += e;
        }
        rinv[t] = 1.f / s;
    }
    __syncthreads();

    if (t < 196) out[(size_t)b * 196 + t] = adj[t] * rinv[t / NR];
}

// ---------------------------------------------------------------------------
extern "C" void kernel_launch(void* const* d_in, const int* in_sizes, int n_in,
                              void* d_out, int out_size)
{
    const float* X    = (const float*)d_in[0];
    const float* area = (const float*)d_in[1];
    const float* co   = (const float*)d_in[2];
    const float* W    = (const float*)d_in[3];
    const float* bias = (const float*)d_in[4];
    float* out = (float*)d_out;

    cudaFuncSetAttribute(gemm_hmma, cudaFuncAttributeMaxDynamicSharedMemorySize, GSMEM);

    convertX<<<(M_TOTAL * (size_t)D) / (256 * 8), 256>>>(X);
    transposeW<<<dim3(D / 32, D / 32), dim3(32, 8)>>>(W);
    gemm_hmma<<<dim3(D / 128, M_TOTAL / 128), 256, GSMEM>>>(bias);
    epilogue_kernel<<<NB, 256>>>(area, co, out);
}